// round 11
// baseline (speedup 1.0000x reference)
#include <cuda_runtime.h>
#include <cuda_fp16.h>
#include <cstdint>

#define NODES 100000
#define IN_F 256
#define OUT_F 256
#define OUT_STRIDE 512
#define MAX_E 3200000
#define SCAN_BLK 1024
#define MAX_SCAN_BLOCKS 128
#define AUX_BLOCKS 1024

// ---------------- static device scratch (no runtime allocation) -------------
__device__ int     g_idx64;
__device__ int     g_cnt[NODES];
__device__ int     g_off[NODES + 1];
__device__ int     g_cursor[NODES];
__device__ int     g_bsum[MAX_SCAN_BLOCKS];
__device__ uint2   g_csr[MAX_E];
__device__ __half2 g_ft16[(size_t)NODES * 128];   // fp16 copy of ft, 51.2 MB

// ---------------- dtype probe -----------------------------------------------
__global__ void detect_kernel(const int* __restrict__ a,
                              const int* __restrict__ b, int E) {
    __shared__ int nz;
    if (threadIdx.x == 0) nz = 0;
    __syncthreads();
    int K = E < 2048 ? E : 2048;
    for (int i = threadIdx.x; i < K; i += blockDim.x) {
        if ((a[2 * i + 1] | b[2 * i + 1]) != 0) nz = 1;
    }
    __syncthreads();
    if (threadIdx.x == 0) g_idx64 = (nz == 0) ? 1 : 0;
}

__global__ void zero_cnt_kernel(int Nn) {
    int i = blockIdx.x * blockDim.x + threadIdx.x;
    if (i < Nn) g_cnt[i] = 0;
}

// ---------------- scan ------------------------------------------------------
__global__ __launch_bounds__(SCAN_BLK)
void scan_reduce_kernel(int Nn) {
    __shared__ int red[32];
    int lane = threadIdx.x & 31;
    int wid  = threadIdx.x >> 5;
    int idx  = blockIdx.x * SCAN_BLK + threadIdx.x;
    int x = (idx < Nn) ? g_cnt[idx] : 0;
    #pragma unroll
    for (int d = 16; d > 0; d >>= 1) x += __shfl_down_sync(0xffffffffu, x, d);
    if (lane == 0) red[wid] = x;
    __syncthreads();
    if (wid == 0) {
        int s = red[lane];
        #pragma unroll
        for (int d = 16; d > 0; d >>= 1) s += __shfl_down_sync(0xffffffffu, s, d);
        if (lane == 0) g_bsum[blockIdx.x] = s;
    }
}

__global__ void scan_tops_kernel(int nb, int Nn) {
    __shared__ int wsum[4];
    int tid  = threadIdx.x;
    int lane = tid & 31;
    int wid  = tid >> 5;
    int x = (tid < nb) ? g_bsum[tid] : 0;
    int v = x;
    #pragma unroll
    for (int d = 1; d < 32; d <<= 1) {
        int t = __shfl_up_sync(0xffffffffu, v, d);
        if (lane >= d) v += t;
    }
    if (lane == 31) wsum[wid] = v;
    __syncthreads();
    int base = 0;
    #pragma unroll
    for (int w = 0; w < 4; w++) if (w < wid) base += wsum[w];
    if (tid < nb) g_bsum[tid] = base + v - x;
    if (tid == 127) g_off[Nn] = base + v;
}

__global__ __launch_bounds__(SCAN_BLK)
void scan_apply_kernel(int Nn) {
    __shared__ int wsum[32];
    int lane = threadIdx.x & 31;
    int wid  = threadIdx.x >> 5;
    int idx  = blockIdx.x * SCAN_BLK + threadIdx.x;
    int x = (idx < Nn) ? g_cnt[idx] : 0;
    int v = x;
    #pragma unroll
    for (int d = 1; d < 32; d <<= 1) {
        int t = __shfl_up_sync(0xffffffffu, v, d);
        if (lane >= d) v += t;
    }
    if (lane == 31) wsum[wid] = v;
    __syncthreads();
    if (wid == 0) {
        int s = wsum[lane];
        #pragma unroll
        for (int d = 1; d < 32; d <<= 1) {
            int t = __shfl_up_sync(0xffffffffu, s, d);
            if (lane >= d) s += t;
        }
        wsum[lane] = s;
    }
    __syncthreads();
    int base = g_bsum[blockIdx.x] + (wid ? wsum[wid - 1] : 0);
    int excl = base + v - x;
    if (idx < Nn) { g_off[idx] = excl; g_cursor[idx] = excl; }
}

// ---------------- fused GEMM rows [rowBase, ...) + aux (hist | scatter) -----
#define AS_K 36

__device__ __forceinline__ uint32_t f2tf32(float f) {
    uint32_t u;
    asm("cvt.rna.tf32.f32 %0, %1;" : "=r"(u) : "f"(f));
    return u;
}

__device__ __forceinline__ void mma_tf32(float& c0, float& c1, float& c2, float& c3,
                                         uint32_t a0, uint32_t a1, uint32_t a2, uint32_t a3,
                                         uint32_t b0, uint32_t b1) {
    asm volatile(
        "mma.sync.aligned.m16n8k8.row.col.f32.tf32.tf32.f32 "
        "{%0,%1,%2,%3}, {%4,%5,%6,%7}, {%8,%9}, {%0,%1,%2,%3};\n"
        : "+f"(c0), "+f"(c1), "+f"(c2), "+f"(c3)
        : "r"(a0), "r"(a1), "r"(a2), "r"(a3), "r"(b0), "r"(b1));
}

// aux_mode 0: hist; 1: scatter
__global__ __launch_bounds__(256)
void gemm_aux_kernel(const float* __restrict__ A,
                     const float* __restrict__ W,
                     const int* __restrict__ esrc,
                     const int* __restrict__ edst,
                     const float* __restrict__ eval_,
                     float* __restrict__ C,
                     int M, int E, int rowBase, int nGemm, int aux_mode) {
    if ((int)blockIdx.x >= nGemm) {
        int stride = g_idx64 ? 2 : 1;
        int nth = (gridDim.x - nGemm) * 256;
        int e0 = (blockIdx.x - nGemm) * 256 + (int)threadIdx.x;
        if (aux_mode == 0) {
            for (int e = e0; e < E; e += nth) {
                int d = edst[e * stride];
                if ((unsigned)d < (unsigned)NODES) atomicAdd(&g_cnt[d], 1);
            }
        } else {
            for (int e = e0; e < E; e += nth) {
                int d = edst[e * stride];
                if ((unsigned)d >= (unsigned)NODES) continue;
                int slot = atomicAdd(&g_cursor[d], 1);
                if ((unsigned)slot < (unsigned)MAX_E)
                    g_csr[slot] = make_uint2((unsigned)esrc[e * stride],
                                             __float_as_uint(eval_[e]));
            }
        }
        return;
    }

    // ---------- GEMM blocks ----------
    __shared__ uint32_t As[128 * AS_K];
    __shared__ uint32_t Bs[128 * AS_K];

    int tid  = threadIdx.x;
    int lane = tid & 31;
    int warp = tid >> 5;
    int wm = (warp & 3) * 32;
    int wn = (warp >> 2) * 64;
    int g = lane >> 2;
    int t = lane & 3;

    int row0 = rowBase + (blockIdx.x >> 1) * 128;
    int n0   = (blockIdx.x & 1) * 128;

    int a_r[4], a_c4[4];
    #pragma unroll
    for (int p = 0; p < 4; p++) {
        int idx = tid + 256 * p;
        a_r[p]  = idx >> 3;
        a_c4[p] = idx & 7;
    }

    float acc[2][8][4];
    #pragma unroll
    for (int mt = 0; mt < 2; mt++)
        #pragma unroll
        for (int nt = 0; nt < 8; nt++)
            #pragma unroll
            for (int c = 0; c < 4; c++) acc[mt][nt][c] = 0.f;

    float4 pa[4];
    #pragma unroll
    for (int p = 0; p < 4; p++) {
        int grow = row0 + a_r[p];
        pa[p] = make_float4(0.f, 0.f, 0.f, 0.f);
        if (grow < M) pa[p] = *(const float4*)&A[(size_t)grow * IN_F + a_c4[p] * 4];
    }

    for (int k0 = 0; k0 < IN_F; k0 += 32) {
        #pragma unroll
        for (int p = 0; p < 4; p++) {
            uint32_t* d = &As[a_r[p] * AS_K + a_c4[p] * 4];
            d[0] = f2tf32(pa[p].x); d[1] = f2tf32(pa[p].y);
            d[2] = f2tf32(pa[p].z); d[3] = f2tf32(pa[p].w);
        }
        #pragma unroll
        for (int p = 0; p < 4; p++) {
            int idx = tid + 256 * p;
            int k  = idx >> 5;
            int c4 = idx & 31;
            float4 v = *(const float4*)&W[(size_t)(k0 + k) * OUT_F + n0 + c4 * 4];
            Bs[(c4 * 4 + 0) * AS_K + k] = f2tf32(v.x);
            Bs[(c4 * 4 + 1) * AS_K + k] = f2tf32(v.y);
            Bs[(c4 * 4 + 2) * AS_K + k] = f2tf32(v.z);
            Bs[(c4 * 4 + 3) * AS_K + k] = f2tf32(v.w);
        }
        __syncthreads();

        if (k0 + 32 < IN_F) {
            #pragma unroll
            for (int p = 0; p < 4; p++) {
                int grow = row0 + a_r[p];
                float4 v = make_float4(0.f, 0.f, 0.f, 0.f);
                if (grow < M)
                    v = *(const float4*)&A[(size_t)grow * IN_F + (k0 + 32) + a_c4[p] * 4];
                pa[p] = v;
            }
        }

        #pragma unroll
        for (int ks = 0; ks < 32; ks += 8) {
            uint32_t af[2][4];
            #pragma unroll
            for (int mt = 0; mt < 2; mt++) {
                int m = wm + mt * 16 + g;
                af[mt][0] = As[m * AS_K + ks + t];
                af[mt][1] = As[(m + 8) * AS_K + ks + t];
                af[mt][2] = As[m * AS_K + ks + t + 4];
                af[mt][3] = As[(m + 8) * AS_K + ks + t + 4];
            }
            #pragma unroll
            for (int nt = 0; nt < 8; nt++) {
                int n = wn + nt * 8 + g;
                uint32_t b0 = Bs[n * AS_K + ks + t];
                uint32_t b1 = Bs[n * AS_K + ks + t + 4];
                #pragma unroll
                for (int mt = 0; mt < 2; mt++)
                    mma_tf32(acc[mt][nt][0], acc[mt][nt][1],
                             acc[mt][nt][2], acc[mt][nt][3],
                             af[mt][0], af[mt][1], af[mt][2], af[mt][3], b0, b1);
            }
        }
        __syncthreads();
    }

    #pragma unroll
    for (int mt = 0; mt < 2; mt++) {
        #pragma unroll
        for (int nt = 0; nt < 8; nt++) {
            int m = row0 + wm + mt * 16 + g;
            int n = n0 + wn + nt * 8 + 2 * t;
            if (m < M) {
                *(float2*)&C[(size_t)m * OUT_STRIDE + n] =
                    make_float2(acc[mt][nt][0], acc[mt][nt][1]);
                g_ft16[(size_t)m * 128 + (n >> 1)] =
                    __floats2half2_rn(acc[mt][nt][0], acc[mt][nt][1]);
            }
            if (m + 8 < M) {
                *(float2*)&C[(size_t)(m + 8) * OUT_STRIDE + n] =
                    make_float2(acc[mt][nt][2], acc[mt][nt][3]);
                g_ft16[(size_t)(m + 8) * 128 + (n >> 1)] =
                    __floats2half2_rn(acc[mt][nt][2], acc[mt][nt][3]);
            }
        }
    }
}

// ---------------- SpMM (full row, uint4 per lane — R9 version) --------------
__device__ __forceinline__ void acc_edge(float2* a, uint4 v, float wgt) {
    float2 f;
    f = __half22float2(*(const __half2*)&v.x);
    a[0].x += wgt * f.x; a[0].y += wgt * f.y;
    f = __half22float2(*(const __half2*)&v.y);
    a[1].x += wgt * f.x; a[1].y += wgt * f.y;
    f = __half22float2(*(const __half2*)&v.z);
    a[2].x += wgt * f.x; a[2].y += wgt * f.y;
    f = __half22float2(*(const __half2*)&v.w);
    a[3].x += wgt * f.x; a[3].y += wgt * f.y;
}

__global__ __launch_bounds__(256)
void spmm_kernel(float* __restrict__ out, int Nn, int E) {
    int node = blockIdx.x * 8 + (threadIdx.x >> 5);
    int lane = threadIdx.x & 31;
    if (node >= Nn) return;

    int beg = g_off[node];
    int end = g_off[node + 1];
    if (beg < 0) beg = 0;
    if (end > E) end = E;
    if (end < beg) end = beg;

    const uint4* ftv = (const uint4*)g_ft16;

    float2 a[4];
    a[0] = make_float2(0.f, 0.f); a[1] = a[0]; a[2] = a[0]; a[3] = a[0];

    int i = beg;
    for (; i + 4 <= end; i += 4) {
        uint2 e0 = g_csr[i + 0];
        uint2 e1 = g_csr[i + 1];
        uint2 e2 = g_csr[i + 2];
        uint2 e3 = g_csr[i + 3];
        uint4 v0 = __ldg(&ftv[(size_t)e0.x * 32 + lane]);
        uint4 v1 = __ldg(&ftv[(size_t)e1.x * 32 + lane]);
        uint4 v2 = __ldg(&ftv[(size_t)e2.x * 32 + lane]);
        uint4 v3 = __ldg(&ftv[(size_t)e3.x * 32 + lane]);
        acc_edge(a, v0, __uint_as_float(e0.y));
        acc_edge(a, v1, __uint_as_float(e1.y));
        acc_edge(a, v2, __uint_as_float(e2.y));
        acc_edge(a, v3, __uint_as_float(e3.y));
    }
    for (; i < end; i++) {
        uint2 e = g_csr[i];
        uint4 v = __ldg(&ftv[(size_t)e.x * 32 + lane]);
        acc_edge(a, v, __uint_as_float(e.y));
    }

    float* dst = &out[(size_t)node * OUT_STRIDE + OUT_F + lane * 8];
    *(float4*)dst       = make_float4(a[0].x, a[0].y, a[1].x, a[1].y);
    *(float4*)(dst + 4) = make_float4(a[2].x, a[2].y, a[3].x, a[3].y);
}

// ---------------- launch ----------------------------------------------------
extern "C" void kernel_launch(void* const* d_in, const int* in_sizes, int n_in,
                              void* d_out, int out_size) {
    const float* input  = (const float*)d_in[0];
    const int*   esrc   = (const int*)d_in[1];
    const int*   edst   = (const int*)d_in[2];
    const float* eval_  = (const float*)d_in[3];
    const float* weight = (const float*)d_in[4];
    float* out = (float*)d_out;

    int M = out_size / OUT_STRIDE;   // 100000
    int E = in_sizes[3];
    int nb = (M + SCAN_BLK - 1) / SCAN_BLK;

    // row split: half the row tiles in each GEMM launch
    int tiles  = (M + 127) / 128;         // 782
    int tiles1 = tiles / 2;               // 391
    int M1     = tiles1 * 128;            // 50048
    int tiles2 = tiles - tiles1;          // 391
    int nG1 = tiles1 * 2;                 // blocks (2 n-halves per row tile)
    int nG2 = tiles2 * 2;

    detect_kernel<<<1, 256>>>(esrc, edst, E);
    zero_cnt_kernel<<<(M + 255) / 256, 256>>>(M);

    // GEMM rows [0, M1) ∥ hist
    gemm_aux_kernel<<<nG1 + AUX_BLOCKS, 256>>>(input, weight, esrc, edst, eval_,
                                               out, M, E, 0, nG1, 0);
    scan_reduce_kernel<<<nb, SCAN_BLK>>>(M);
    scan_tops_kernel<<<1, 128>>>(nb, M);
    scan_apply_kernel<<<nb, SCAN_BLK>>>(M);

    // GEMM rows [M1, M) ∥ scatter
    gemm_aux_kernel<<<nG2 + AUX_BLOCKS, 256>>>(input, weight, esrc, edst, eval_,
                                               out, M, E, M1, nG2, 1);

    spmm_kernel<<<(M + 7) / 8, 256>>>(out, M, E);
}

// round 13
// speedup vs baseline: 1.7267x; 1.7267x over previous
#include <cuda_runtime.h>
#include <cuda_fp16.h>
#include <cstdint>

#define NODES 100000
#define IN_F 256
#define OUT_F 256
#define OUT_STRIDE 512
#define MAX_E 3200000
#define SCAN_BLK 1024
#define MAX_SCAN_BLOCKS 128

// ---------------- static device scratch (no runtime allocation) -------------
__device__ int     g_idx64;
__device__ int     g_cnt[NODES];
__device__ int     g_off[NODES + 1];
__device__ int     g_cursor[NODES];
__device__ int     g_bsum[MAX_SCAN_BLOCKS];
__device__ uint2   g_csr[MAX_E];
__device__ __half2 g_ft16[(size_t)NODES * 128];   // fp16 copy of ft, 51.2 MB

// ---------------- dtype probe -----------------------------------------------
__global__ void detect_kernel(const int* __restrict__ a,
                              const int* __restrict__ b, int E) {
    __shared__ int nz;
    if (threadIdx.x == 0) nz = 0;
    __syncthreads();
    int K = E < 2048 ? E : 2048;
    for (int i = threadIdx.x; i < K; i += blockDim.x) {
        if ((a[2 * i + 1] | b[2 * i + 1]) != 0) nz = 1;
    }
    __syncthreads();
    if (threadIdx.x == 0) g_idx64 = (nz == 0) ? 1 : 0;
}

__global__ void zero_cnt_kernel(int Nn) {
    int i = blockIdx.x * blockDim.x + threadIdx.x;
    if (i < Nn) g_cnt[i] = 0;
}

// ---------------- CSR build --------------------------------------------------
__global__ void hist_kernel(const int* __restrict__ dst, int E) {
    int stride = g_idx64 ? 2 : 1;
    int e = blockIdx.x * blockDim.x + threadIdx.x;
    if (e < E) {
        int d = dst[e * stride];
        if ((unsigned)d < (unsigned)NODES) atomicAdd(&g_cnt[d], 1);
    }
}

__global__ __launch_bounds__(SCAN_BLK)
void scan_reduce_kernel(int Nn) {
    __shared__ int red[32];
    int lane = threadIdx.x & 31;
    int wid  = threadIdx.x >> 5;
    int idx  = blockIdx.x * SCAN_BLK + threadIdx.x;
    int x = (idx < Nn) ? g_cnt[idx] : 0;
    #pragma unroll
    for (int d = 16; d > 0; d >>= 1) x += __shfl_down_sync(0xffffffffu, x, d);
    if (lane == 0) red[wid] = x;
    __syncthreads();
    if (wid == 0) {
        int s = red[lane];
        #pragma unroll
        for (int d = 16; d > 0; d >>= 1) s += __shfl_down_sync(0xffffffffu, s, d);
        if (lane == 0) g_bsum[blockIdx.x] = s;
    }
}

__global__ void scan_tops_kernel(int nb, int Nn) {
    __shared__ int wsum[4];
    int tid  = threadIdx.x;
    int lane = tid & 31;
    int wid  = tid >> 5;
    int x = (tid < nb) ? g_bsum[tid] : 0;
    int v = x;
    #pragma unroll
    for (int d = 1; d < 32; d <<= 1) {
        int t = __shfl_up_sync(0xffffffffu, v, d);
        if (lane >= d) v += t;
    }
    if (lane == 31) wsum[wid] = v;
    __syncthreads();
    int base = 0;
    #pragma unroll
    for (int w = 0; w < 4; w++) if (w < wid) base += wsum[w];
    if (tid < nb) g_bsum[tid] = base + v - x;
    if (tid == 127) g_off[Nn] = base + v;
}

__global__ __launch_bounds__(SCAN_BLK)
void scan_apply_kernel(int Nn) {
    __shared__ int wsum[32];
    int lane = threadIdx.x & 31;
    int wid  = threadIdx.x >> 5;
    int idx  = blockIdx.x * SCAN_BLK + threadIdx.x;
    int x = (idx < Nn) ? g_cnt[idx] : 0;
    int v = x;
    #pragma unroll
    for (int d = 1; d < 32; d <<= 1) {
        int t = __shfl_up_sync(0xffffffffu, v, d);
        if (lane >= d) v += t;
    }
    if (lane == 31) wsum[wid] = v;
    __syncthreads();
    if (wid == 0) {
        int s = wsum[lane];
        #pragma unroll
        for (int d = 1; d < 32; d <<= 1) {
            int t = __shfl_up_sync(0xffffffffu, s, d);
            if (lane >= d) s += t;
        }
        wsum[lane] = s;
    }
    __syncthreads();
    int base = g_bsum[blockIdx.x] + (wid ? wsum[wid - 1] : 0);
    int excl = base + v - x;
    if (idx < Nn) { g_off[idx] = excl; g_cursor[idx] = excl; }
}

__global__ void scatter_kernel(const int* __restrict__ src,
                               const int* __restrict__ dst,
                               const float* __restrict__ val, int E) {
    int stride = g_idx64 ? 2 : 1;
    int e = blockIdx.x * blockDim.x + threadIdx.x;
    if (e >= E) return;
    int d = dst[e * stride];
    if ((unsigned)d >= (unsigned)NODES) return;
    int slot = atomicAdd(&g_cursor[d], 1);
    if ((unsigned)slot < (unsigned)MAX_E)
        g_csr[slot] = make_uint2((unsigned)src[e * stride],
                                 __float_as_uint(val[e]));
}

// ---------------- fp16 tensor-core GEMM: out[:, 0:256] = input @ W ----------
// 128x128 tile, BK=32, 8 warps (4 m x 2 n), warp tile 32x64,
// mma.sync.m16n8k16 f16 inputs, fp32 accumulate.
// AS_K = 40 halves (80B row stride = 20 banks -> conflict-free fragments).
#define AS_K 40

__device__ __forceinline__ void mma_fp16(float& c0, float& c1, float& c2, float& c3,
                                         uint32_t a0, uint32_t a1, uint32_t a2, uint32_t a3,
                                         uint32_t b0, uint32_t b1) {
    asm volatile(
        "mma.sync.aligned.m16n8k16.row.col.f32.f16.f16.f32 "
        "{%0,%1,%2,%3}, {%4,%5,%6,%7}, {%8,%9}, {%0,%1,%2,%3};\n"
        : "+f"(c0), "+f"(c1), "+f"(c2), "+f"(c3)
        : "r"(a0), "r"(a1), "r"(a2), "r"(a3), "r"(b0), "r"(b1));
}

__global__ __launch_bounds__(256)
void gemm_fp16_kernel(const float* __restrict__ A,
                      const float* __restrict__ W,
                      float* __restrict__ C,
                      int M) {
    __shared__ __half As[128 * AS_K];   // [m][k]
    __shared__ __half Bs[128 * AS_K];   // [n][k] (transposed)

    int tid  = threadIdx.x;
    int lane = tid & 31;
    int warp = tid >> 5;
    int wm = (warp & 3) * 32;
    int wn = (warp >> 2) * 64;
    int g = lane >> 2;
    int t = lane & 3;

    int row0 = (blockIdx.x >> 1) * 128;
    int n0   = (blockIdx.x & 1) * 128;

    float acc[2][8][4];
    #pragma unroll
    for (int mt = 0; mt < 2; mt++)
        #pragma unroll
        for (int nt = 0; nt < 8; nt++)
            #pragma unroll
            for (int c = 0; c < 4; c++) acc[mt][nt][c] = 0.f;

    for (int k0 = 0; k0 < IN_F; k0 += 32) {
        // A tile: 128 rows x 32 halves (4 float4 loads / thread)
        #pragma unroll
        for (int p = 0; p < 4; p++) {
            int idx = tid + 256 * p;
            int r  = idx >> 3;
            int c4 = idx & 7;
            int grow = row0 + r;
            float4 v = make_float4(0.f, 0.f, 0.f, 0.f);
            if (grow < M) v = *(const float4*)&A[(size_t)grow * IN_F + k0 + c4 * 4];
            __half2* d = (__half2*)&As[r * AS_K + c4 * 4];
            d[0] = __floats2half2_rn(v.x, v.y);
            d[1] = __floats2half2_rn(v.z, v.w);
        }
        // B tile: 32 k rows x 128 n, transposed into Bs[n][k]
        #pragma unroll
        for (int p = 0; p < 4; p++) {
            int idx = tid + 256 * p;
            int k  = idx >> 5;
            int c4 = idx & 31;
            float4 v = *(const float4*)&W[(size_t)(k0 + k) * OUT_F + n0 + c4 * 4];
            Bs[(c4 * 4 + 0) * AS_K + k] = __float2half_rn(v.x);
            Bs[(c4 * 4 + 1) * AS_K + k] = __float2half_rn(v.y);
            Bs[(c4 * 4 + 2) * AS_K + k] = __float2half_rn(v.z);
            Bs[(c4 * 4 + 3) * AS_K + k] = __float2half_rn(v.w);
        }
        __syncthreads();

        #pragma unroll
        for (int ks = 0; ks < 32; ks += 16) {
            uint32_t af[2][4];
            #pragma unroll
            for (int mt = 0; mt < 2; mt++) {
                int m = wm + mt * 16 + g;
                af[mt][0] = *(const uint32_t*)&As[m * AS_K + ks + 2 * t];
                af[mt][1] = *(const uint32_t*)&As[(m + 8) * AS_K + ks + 2 * t];
                af[mt][2] = *(const uint32_t*)&As[m * AS_K + ks + 2 * t + 8];
                af[mt][3] = *(const uint32_t*)&As[(m + 8) * AS_K + ks + 2 * t + 8];
            }
            #pragma unroll
            for (int nt = 0; nt < 8; nt++) {
                int n = wn + nt * 8 + g;
                uint32_t b0 = *(const uint32_t*)&Bs[n * AS_K + ks + 2 * t];
                uint32_t b1 = *(const uint32_t*)&Bs[n * AS_K + ks + 2 * t + 8];
                #pragma unroll
                for (int mt = 0; mt < 2; mt++)
                    mma_fp16(acc[mt][nt][0], acc[mt][nt][1],
                             acc[mt][nt][2], acc[mt][nt][3],
                             af[mt][0], af[mt][1], af[mt][2], af[mt][3], b0, b1);
            }
        }
        __syncthreads();
    }

    // store: c0/c1 at (m, 2t), c2/c3 at (m+8, 2t); fp32 out + fp16 shadow
    #pragma unroll
    for (int mt = 0; mt < 2; mt++) {
        #pragma unroll
        for (int nt = 0; nt < 8; nt++) {
            int m = row0 + wm + mt * 16 + g;
            int n = n0 + wn + nt * 8 + 2 * t;
            if (m < M) {
                *(float2*)&C[(size_t)m * OUT_STRIDE + n] =
                    make_float2(acc[mt][nt][0], acc[mt][nt][1]);
                g_ft16[(size_t)m * 128 + (n >> 1)] =
                    __floats2half2_rn(acc[mt][nt][0], acc[mt][nt][1]);
            }
            if (m + 8 < M) {
                *(float2*)&C[(size_t)(m + 8) * OUT_STRIDE + n] =
                    make_float2(acc[mt][nt][2], acc[mt][nt][3]);
                g_ft16[(size_t)(m + 8) * 128 + (n >> 1)] =
                    __floats2half2_rn(acc[mt][nt][2], acc[mt][nt][3]);
            }
        }
    }
}

// ---------------- SpMM: out[:,256:512] = segment_sum(val * ft16[src]) -------
__device__ __forceinline__ void acc_edge(float2* a, uint4 v, float wgt) {
    float2 f;
    f = __half22float2(*(const __half2*)&v.x);
    a[0].x += wgt * f.x; a[0].y += wgt * f.y;
    f = __half22float2(*(const __half2*)&v.y);
    a[1].x += wgt * f.x; a[1].y += wgt * f.y;
    f = __half22float2(*(const __half2*)&v.z);
    a[2].x += wgt * f.x; a[2].y += wgt * f.y;
    f = __half22float2(*(const __half2*)&v.w);
    a[3].x += wgt * f.x; a[3].y += wgt * f.y;
}

__global__ __launch_bounds__(256)
void spmm_kernel(float* __restrict__ out, int Nn, int E) {
    int node = blockIdx.x * 8 + (threadIdx.x >> 5);
    int lane = threadIdx.x & 31;
    if (node >= Nn) return;

    int beg = g_off[node];
    int end = g_off[node + 1];
    if (beg < 0) beg = 0;
    if (end > E) end = E;
    if (end < beg) end = beg;

    const uint4* ftv = (const uint4*)g_ft16;

    float2 a[4];
    a[0] = make_float2(0.f, 0.f); a[1] = a[0]; a[2] = a[0]; a[3] = a[0];

    int i = beg;
    for (; i + 4 <= end; i += 4) {
        uint2 e0 = g_csr[i + 0];
        uint2 e1 = g_csr[i + 1];
        uint2 e2 = g_csr[i + 2];
        uint2 e3 = g_csr[i + 3];
        uint4 v0 = __ldg(&ftv[(size_t)e0.x * 32 + lane]);
        uint4 v1 = __ldg(&ftv[(size_t)e1.x * 32 + lane]);
        uint4 v2 = __ldg(&ftv[(size_t)e2.x * 32 + lane]);
        uint4 v3 = __ldg(&ftv[(size_t)e3.x * 32 + lane]);
        acc_edge(a, v0, __uint_as_float(e0.y));
        acc_edge(a, v1, __uint_as_float(e1.y));
        acc_edge(a, v2, __uint_as_float(e2.y));
        acc_edge(a, v3, __uint_as_float(e3.y));
    }
    for (; i < end; i++) {
        uint2 e = g_csr[i];
        uint4 v = __ldg(&ftv[(size_t)e.x * 32 + lane]);
        acc_edge(a, v, __uint_as_float(e.y));
    }

    float* dst = &out[(size_t)node * OUT_STRIDE + OUT_F + lane * 8];
    *(float4*)dst       = make_float4(a[0].x, a[0].y, a[1].x, a[1].y);
    *(float4*)(dst + 4) = make_float4(a[2].x, a[2].y, a[3].x, a[3].y);
}

// ---------------- launch ------------------------------------------------------
extern "C" void kernel_launch(void* const* d_in, const int* in_sizes, int n_in,
                              void* d_out, int out_size) {
    const float* input  = (const float*)d_in[0];
    const int*   esrc   = (const int*)d_in[1];
    const int*   edst   = (const int*)d_in[2];
    const float* eval_  = (const float*)d_in[3];
    const float* weight = (const float*)d_in[4];
    float* out = (float*)d_out;

    int M = out_size / OUT_STRIDE;   // 100000
    int E = in_sizes[3];
    int nb = (M + SCAN_BLK - 1) / SCAN_BLK;
    int nGemm = ((M + 127) / 128) * 2;

    // one-time side stream + events (no device memory involved)
    static cudaStream_t s2 = nullptr;
    static cudaEvent_t evFork = nullptr, evJoin = nullptr;
    if (!s2) {
        cudaStreamCreateWithFlags(&s2, cudaStreamNonBlocking);
        cudaEventCreateWithFlags(&evFork, cudaEventDisableTiming);
        cudaEventCreateWithFlags(&evJoin, cudaEventDisableTiming);
    }

    // prefix on main stream (side chain depends on detect/zero)
    detect_kernel<<<1, 256>>>(esrc, edst, E);
    zero_cnt_kernel<<<(M + 255) / 256, 256>>>(M);

    // fork: CSR build on side stream, GEMM on main stream
    cudaEventRecord(evFork, 0);
    cudaStreamWaitEvent(s2, evFork, 0);

    hist_kernel<<<(E + 255) / 256, 256, 0, s2>>>(edst, E);
    scan_reduce_kernel<<<nb, SCAN_BLK, 0, s2>>>(M);
    scan_tops_kernel<<<1, 128, 0, s2>>>(nb, M);
    scan_apply_kernel<<<nb, SCAN_BLK, 0, s2>>>(M);
    scatter_kernel<<<(E + 255) / 256, 256, 0, s2>>>(esrc, edst, eval_, E);
    cudaEventRecord(evJoin, s2);

    gemm_fp16_kernel<<<nGemm, 256>>>(input, weight, out, M);

    // join: SpMM needs both GEMM (ft16) and CSR
    cudaStreamWaitEvent(0, evJoin, 0);
    spmm_kernel<<<(M + 7) / 8, 256>>>(out, M, E);
}